// round 4
// baseline (speedup 1.0000x reference)
#include <cuda_runtime.h>
#include <cuda_fp16.h>
#include <cstdint>
#include <cstddef>

// ============================================================================
// Problem dims: out[8192,4096] = SwiGLU-MLP(x[8192,4096]) with ternary weights
//   gate = (x @ Wg^T)*ag ; up = (x @ Wu^T)*au ; h = silu(gate)*up
//   out  = (h @ Wd^T)*ad
// All tensor-core work via mma.sync (m16n8k16 fp16->fp32): the harness compiles
// through compute_100 PTX, which rejects every tcgen05 instruction.
// ============================================================================
#define HID   4096
#define INTER 11008
#define MTOK  8192

// ============================================================================
// Device scratch (allocation rule: __device__ globals only)
// ============================================================================
__device__ __half g_x16 [(size_t)MTOK  * HID];     //  64 MB
__device__ __half g_wg16[(size_t)INTER * HID];     //  86 MB
__device__ __half g_wu16[(size_t)INTER * HID];     //  86 MB
__device__ __half g_wd16[(size_t)HID   * INTER];   //  86 MB
__device__ __half g_gate[(size_t)MTOK  * INTER];   // 180 MB (later holds h)
__device__ __half g_up  [(size_t)MTOK  * INTER];   // 180 MB

// ============================================================================
// PTX helpers (sm_100-baseline only: cp.async, ldmatrix, mma.sync)
// ============================================================================
__device__ __forceinline__ uint32_t smem_u32(const void* p) {
    uint32_t a;
    asm("{ .reg .u64 t; cvta.to.shared.u64 t, %1; cvt.u32.u64 %0, t; }"
        : "=r"(a) : "l"(p));
    return a;
}

__device__ __forceinline__ void cp_async16(uint32_t s, const void* g) {
    asm volatile("cp.async.cg.shared.global [%0], [%1], 16;" :: "r"(s), "l"(g));
}
#define CP_COMMIT() asm volatile("cp.async.commit_group;" ::: "memory")
#define CP_WAIT1()  asm volatile("cp.async.wait_group 1;"  ::: "memory")

__device__ __forceinline__ void ldsm4(uint32_t* r, uint32_t addr) {
    asm volatile("ldmatrix.sync.aligned.m8n8.x4.shared.b16 {%0,%1,%2,%3}, [%4];"
        : "=r"(r[0]), "=r"(r[1]), "=r"(r[2]), "=r"(r[3]) : "r"(addr));
}

__device__ __forceinline__ void mma16816(float* c, const uint32_t* a,
                                         uint32_t b0, uint32_t b1) {
    asm volatile(
        "mma.sync.aligned.m16n8k16.row.col.f32.f16.f16.f32 "
        "{%0,%1,%2,%3}, {%4,%5,%6,%7}, {%8,%9}, {%0,%1,%2,%3};"
        : "+f"(c[0]), "+f"(c[1]), "+f"(c[2]), "+f"(c[3])
        : "r"(a[0]), "r"(a[1]), "r"(a[2]), "r"(a[3]), "r"(b0), "r"(b1));
}

// ============================================================================
// Tile loader: R rows x 64 halves (128 B) per row, XOR-swizzled smem layout.
// chunk = 16 B unit; smem_off = row*128 + ((chunk ^ (row&7)) << 4).
// This makes both the cp.async stores (8 consecutive threads fill one 128 B
// row) and the ldmatrix reads (8 lanes hit 8 distinct 16 B banks) conflict-free.
// ============================================================================
template<int R>
__device__ __forceinline__ void load_tile(uint32_t sbase, const __half* g,
                                          int row0, int k0, int ldk) {
    int t = threadIdx.x;
    #pragma unroll
    for (int i = 0; i < R / 32; i++) {       // R*8 chunks / 256 threads
        int ch = t + i * 256;
        int r = ch >> 3, c = ch & 7;
        cp_async16(sbase + r * 128 + (uint32_t)((c ^ (r & 7)) << 4),
                   g + (size_t)(row0 + r) * ldk + k0 + c * 8);
    }
}

// ============================================================================
// GEMM: C[m,n] = (sum_k A[m,k] * B[n,k]) * alpha[n]
//   CTA tile 128x256, BK=64, 3-stage cp.async pipeline, 8 warps (2m x 4n),
//   warp tile 64x64. A row-major [M,K] fp16; B row-major [N,K] fp16 (i.e. the
//   torch Linear layout -> mma row.col with both operands ldmatrix non-trans).
// ============================================================================
#define STG_BYTES 49152u   // A 16 KB + B 32 KB
#define GEMM_SMEM (3 * 49152)

template<bool F32OUT>
__global__ void __launch_bounds__(256, 1)
gemm_kernel(const __half* __restrict__ A, const __half* __restrict__ B,
            const float* __restrict__ alpha, void* __restrict__ Cout,
            int N, int K) {
    extern __shared__ char smem[];
    const uint32_t sb = smem_u32(smem);
    const int m0 = blockIdx.x * 128;
    const int n0 = blockIdx.y * 256;
    const int l   = threadIdx.x & 31;
    const int wid = threadIdx.x >> 5;
    const int wm = (wid & 1) * 64;       // warp m offset within CTA tile
    const int wn = (wid >> 1) * 64;      // warp n offset
    const int KT = K >> 6;               // 64-K tiles

    // prologue: stages 0 and 1
    load_tile<128>(sb + 0 * STG_BYTES,          A, m0, 0,  K);
    load_tile<256>(sb + 0 * STG_BYTES + 16384u, B, n0, 0,  K);
    CP_COMMIT();
    load_tile<128>(sb + 1 * STG_BYTES,          A, m0, 64, K);
    load_tile<256>(sb + 1 * STG_BYTES + 16384u, B, n0, 64, K);
    CP_COMMIT();

    float acc[4][8][4];
    #pragma unroll
    for (int i = 0; i < 4; i++)
        #pragma unroll
        for (int j = 0; j < 8; j++)
            #pragma unroll
            for (int q = 0; q < 4; q++) acc[i][j][q] = 0.f;

    // ldmatrix per-lane addressing: row = base + (l&15), k-chunk += (l>>4)
    const int lr = l & 15, lc = l >> 4, lx = l & 7;

    int st = 0;
    for (int kt = 0; kt < KT; kt++) {
        CP_WAIT1();                       // stage kt finished
        __syncthreads();
        if (kt + 2 < KT) {
            int s2 = kt + 2; s2 -= (s2 >= 3) ? 3 : 0; s2 = (kt + 2) % 3;
            uint32_t base2 = sb + (uint32_t)s2 * STG_BYTES;
            load_tile<128>(base2,          A, m0, (kt + 2) * 64, K);
            load_tile<256>(base2 + 16384u, B, n0, (kt + 2) * 64, K);
        }
        CP_COMMIT();                      // (possibly empty) group keeps counts aligned

        const uint32_t a_base = sb + (uint32_t)st * STG_BYTES + (uint32_t)(wm + lr) * 128u;
        const uint32_t b_base = sb + (uint32_t)st * STG_BYTES + 16384u + (uint32_t)(wn + lr) * 128u;

        #pragma unroll
        for (int ks = 0; ks < 4; ks++) {              // 4 x K16 per 64-K tile
            const uint32_t ca = (uint32_t)(((ks * 2 + lc) ^ lx) << 4);
            uint32_t av[4][4], bv[4][4];
            #pragma unroll
            for (int mt = 0; mt < 4; mt++) ldsm4(av[mt], a_base + mt * 2048u + ca);
            #pragma unroll
            for (int nb = 0; nb < 4; nb++) ldsm4(bv[nb], b_base + nb * 2048u + ca);
            #pragma unroll
            for (int mt = 0; mt < 4; mt++)
                #pragma unroll
                for (int nb = 0; nb < 4; nb++) {
                    mma16816(acc[mt][nb * 2 + 0], av[mt], bv[nb][0], bv[nb][2]);
                    mma16816(acc[mt][nb * 2 + 1], av[mt], bv[nb][1], bv[nb][3]);
                }
        }
        if (++st == 3) st = 0;
    }

    // epilogue: c0,c1 -> (row, col..col+1); c2,c3 -> (row+8, ...)
    const int r0 = l >> 2, c0 = (l & 3) * 2;
    #pragma unroll
    for (int mt = 0; mt < 4; mt++) {
        int gm = m0 + wm + mt * 16 + r0;
        #pragma unroll
        for (int nf = 0; nf < 8; nf++) {
            int gn = n0 + wn + nf * 8 + c0;
            float s0 = alpha[gn], s1 = alpha[gn + 1];
            float* a4 = acc[mt][nf];
            if (F32OUT) {
                float* o = (float*)Cout;
                *reinterpret_cast<float2*>(o + (size_t)gm * N + gn) =
                    make_float2(a4[0] * s0, a4[1] * s1);
                *reinterpret_cast<float2*>(o + (size_t)(gm + 8) * N + gn) =
                    make_float2(a4[2] * s0, a4[3] * s1);
            } else {
                __half* o = (__half*)Cout;
                *reinterpret_cast<__half2*>(o + (size_t)gm * N + gn) =
                    __floats2half2_rn(a4[0] * s0, a4[1] * s1);
                *reinterpret_cast<__half2*>(o + (size_t)(gm + 8) * N + gn) =
                    __floats2half2_rn(a4[2] * s0, a4[3] * s1);
            }
        }
    }
}

// ============================================================================
// fp32 -> fp16 conversion (vectorized, grid-stride)
// ============================================================================
__global__ void cvt_f32_f16(const float* __restrict__ in, __half* __restrict__ out,
                            size_t n4) {
    size_t i = (size_t)blockIdx.x * blockDim.x + threadIdx.x;
    size_t stride = (size_t)gridDim.x * blockDim.x;
    for (; i < n4; i += stride) {
        float4 v = reinterpret_cast<const float4*>(in)[i];
        __half2 lo = __floats2half2_rn(v.x, v.y);
        __half2 hi = __floats2half2_rn(v.z, v.w);
        uint2 o;
        o.x = *reinterpret_cast<uint32_t*>(&lo);
        o.y = *reinterpret_cast<uint32_t*>(&hi);
        reinterpret_cast<uint2*>(out)[i] = o;
    }
}

// ============================================================================
// SwiGLU elementwise: gate <- silu(gate) * up   (fp16 in/out, in-place on gate)
// ============================================================================
__global__ void swiglu_kernel(__half2* __restrict__ g, const __half2* __restrict__ u,
                              size_t n2) {
    size_t i = (size_t)blockIdx.x * blockDim.x + threadIdx.x;
    size_t stride = (size_t)gridDim.x * blockDim.x;
    for (; i < n2; i += stride) {
        float2 gf = __half22float2(g[i]);
        float2 uf = __half22float2(u[i]);
        float h0 = (gf.x / (1.0f + __expf(-gf.x))) * uf.x;
        float h1 = (gf.y / (1.0f + __expf(-gf.y))) * uf.y;
        g[i] = __floats2half2_rn(h0, h1);
    }
}

// ============================================================================
// Host side
// ============================================================================
extern "C" void kernel_launch(void* const* d_in, const int* in_sizes, int n_in,
                              void* d_out, int out_size) {
    const float* x  = (const float*)d_in[0];
    const float* Wg = (const float*)d_in[1];
    const float* Wu = (const float*)d_in[2];
    const float* Wd = (const float*)d_in[3];
    const float* ag = (const float*)d_in[4];
    const float* au = (const float*)d_in[5];
    const float* ad = (const float*)d_in[6];
    float* out = (float*)d_out;

    void *px, *pwg, *pwu, *pwd, *pg, *pu;
    cudaGetSymbolAddress(&px,  g_x16);
    cudaGetSymbolAddress(&pwg, g_wg16);
    cudaGetSymbolAddress(&pwu, g_wu16);
    cudaGetSymbolAddress(&pwd, g_wd16);
    cudaGetSymbolAddress(&pg,  g_gate);
    cudaGetSymbolAddress(&pu,  g_up);

    cudaFuncSetAttribute(gemm_kernel<false>,
                         cudaFuncAttributeMaxDynamicSharedMemorySize, GEMM_SMEM);
    cudaFuncSetAttribute(gemm_kernel<true>,
                         cudaFuncAttributeMaxDynamicSharedMemorySize, GEMM_SMEM);

    // fp32 -> fp16
    cvt_f32_f16<<<2048, 256>>>(x,  (__half*)px,  (size_t)MTOK  * HID   / 4);
    cvt_f32_f16<<<2048, 256>>>(Wg, (__half*)pwg, (size_t)INTER * HID   / 4);
    cvt_f32_f16<<<2048, 256>>>(Wu, (__half*)pwu, (size_t)INTER * HID   / 4);
    cvt_f32_f16<<<2048, 256>>>(Wd, (__half*)pwd, (size_t)HID   * INTER / 4);

    // gate = (x @ Wg^T) * ag   [fp16 out]
    gemm_kernel<false><<<dim3(MTOK / 128, INTER / 256), 256, GEMM_SMEM>>>(
        (const __half*)px, (const __half*)pwg, ag, pg, INTER, HID);
    // up = (x @ Wu^T) * au     [fp16 out]
    gemm_kernel<false><<<dim3(MTOK / 128, INTER / 256), 256, GEMM_SMEM>>>(
        (const __half*)px, (const __half*)pwu, au, pu, INTER, HID);

    // h = silu(gate) * up  (in-place into gate buffer)
    swiglu_kernel<<<2048, 256>>>((__half2*)pg, (const __half2*)pu,
                                 (size_t)MTOK * INTER / 2);

    // out = (h @ Wd^T) * ad    [fp32 out]
    gemm_kernel<true><<<dim3(MTOK / 128, HID / 256), 256, GEMM_SMEM>>>(
        (const __half*)pg, (const __half*)pwd, ad, out, HID, INTER);
}

// round 6
// speedup vs baseline: 1.0276x; 1.0276x over previous
#include <cuda_runtime.h>
#include <cuda_fp16.h>
#include <cstdint>
#include <cstddef>

// ============================================================================
// out[8192,4096] = SwiGLU-MLP(x[8192,4096]) with ternary weights.
//   gate = (x @ Wg^T)*ag ; up = (x @ Wu^T)*au ; h = silu(gate)*up
//   out  = (h @ Wd^T)*ad
// mma.sync m16n8k16 fp16->fp32 (harness compiles via compute_100: no tcgen05).
// R4 passed at 6640us with 256-thread/8-warp CTAs (2 warps/SMSP) and separate
// gate/up GEMMs + swiglu pass. This round (resubmit of R5, which hit broker
// infra failure): 512-thread/16-warp CTAs (4 warps/SMSP for latency hiding)
// and gate+up fused into one kernel (A loaded once, h produced directly,
// swiglu pass and 720MB of intermediates eliminated).
// ============================================================================
#define HID   4096
#define INTER 11008
#define MTOK  8192

// ============================================================================
// Device scratch (allocation rule: __device__ globals only)
// ============================================================================
__device__ __half g_x16 [(size_t)MTOK  * HID];     //  64 MB
__device__ __half g_wg16[(size_t)INTER * HID];     //  86 MB
__device__ __half g_wu16[(size_t)INTER * HID];     //  86 MB
__device__ __half g_wd16[(size_t)HID   * INTER];   //  86 MB
__device__ __half g_h16 [(size_t)MTOK  * INTER];   // 172 MB

// ============================================================================
// PTX helpers (sm_100-baseline: cp.async, ldmatrix, mma.sync)
// ============================================================================
__device__ __forceinline__ uint32_t smem_u32(const void* p) {
    uint32_t a;
    asm("{ .reg .u64 t; cvta.to.shared.u64 t, %1; cvt.u32.u64 %0, t; }"
        : "=r"(a) : "l"(p));
    return a;
}

__device__ __forceinline__ void cp_async16(uint32_t s, const void* g) {
    asm volatile("cp.async.cg.shared.global [%0], [%1], 16;" :: "r"(s), "l"(g));
}
#define CP_COMMIT() asm volatile("cp.async.commit_group;" ::: "memory")
#define CP_WAIT1()  asm volatile("cp.async.wait_group 1;"  ::: "memory")

__device__ __forceinline__ void ldsm4(uint32_t* r, uint32_t addr) {
    asm volatile("ldmatrix.sync.aligned.m8n8.x4.shared.b16 {%0,%1,%2,%3}, [%4];"
        : "=r"(r[0]), "=r"(r[1]), "=r"(r[2]), "=r"(r[3]) : "r"(addr));
}

__device__ __forceinline__ void mma16816(float* c, const uint32_t* a,
                                         uint32_t b0, uint32_t b1) {
    asm volatile(
        "mma.sync.aligned.m16n8k16.row.col.f32.f16.f16.f32 "
        "{%0,%1,%2,%3}, {%4,%5,%6,%7}, {%8,%9}, {%0,%1,%2,%3};"
        : "+f"(c[0]), "+f"(c[1]), "+f"(c[2]), "+f"(c[3])
        : "r"(a[0]), "r"(a[1]), "r"(a[2]), "r"(a[3]), "r"(b0), "r"(b1));
}

// ============================================================================
// Tile loader: R rows x 64 halves (128 B) per row, XOR-swizzled smem layout.
// chunk = 16 B unit; smem_off = row*128 + ((chunk ^ (row&7)) << 4).
// cp.async stores (8 threads per 128 B row) and ldmatrix reads (8 lanes,
// 8 distinct 16 B banks) are both conflict-free. Verified correct in R4.
// ============================================================================
template<int THREADS, int R>
__device__ __forceinline__ void load_tile(uint32_t sbase, const __half* g,
                                          int row0, int k0, int ldk) {
    int t = threadIdx.x;
    #pragma unroll
    for (int i = 0; i < R * 8 / THREADS; i++) {
        int ch = t + i * THREADS;
        int r = ch >> 3, c = ch & 7;
        cp_async16(sbase + r * 128 + (uint32_t)((c ^ (r & 7)) << 4),
                   g + (size_t)(row0 + r) * ldk + k0 + c * 8);
    }
}

__device__ __forceinline__ float sigmoidf_fast(float v) {
    return 1.0f / (1.0f + __expf(-v));
}

// ============================================================================
// Fused gate+up GEMM + SwiGLU.
//   CTA tile 128(M) x 128(N), computing BOTH gate and up accumulators from one
//   A pipeline. 512 threads = 16 warps in a 4m x 4n grid; warp tile 32x32 per
//   matrix (acc 32+32 fp32/thread). 3-stage cp.async pipeline, stage = 48 KB
//   (A 16K + Wg 16K + Wu 16K). Epilogue: h = silu(g*ag)*(u*au) -> fp16.
// Grid: x = m-tile (fast) so concurrent CTAs share weight panels; x (64 MB
// fp16) stays L2-resident across n-groups.
// ============================================================================
#define STG1 49152u
#define SMEM1 (3 * 49152)

__global__ void __launch_bounds__(512, 1)
gemm1_fused(const __half* __restrict__ X, const __half* __restrict__ WG,
            const __half* __restrict__ WU, const float* __restrict__ ag,
            const float* __restrict__ au, __half* __restrict__ H) {
    extern __shared__ char smem[];
    const uint32_t sb = smem_u32(smem);
    const int m0 = blockIdx.x * 128;
    const int n0 = blockIdx.y * 128;
    const int l   = threadIdx.x & 31;
    const int wid = threadIdx.x >> 5;
    const int wm = (wid & 3) * 32;
    const int wn = (wid >> 2) * 32;
    const int KT = HID >> 6;

    // prologue: stages 0, 1
    #pragma unroll
    for (int s = 0; s < 2; s++) {
        uint32_t base = sb + (uint32_t)s * STG1;
        load_tile<512, 128>(base,           X,  m0, s * 64, HID);
        load_tile<512, 128>(base + 16384u,  WG, n0, s * 64, HID);
        load_tile<512, 128>(base + 32768u,  WU, n0, s * 64, HID);
        CP_COMMIT();
    }

    float accg[2][4][4], accu[2][4][4];
    #pragma unroll
    for (int i = 0; i < 2; i++)
        #pragma unroll
        for (int j = 0; j < 4; j++)
            #pragma unroll
            for (int q = 0; q < 4; q++) { accg[i][j][q] = 0.f; accu[i][j][q] = 0.f; }

    const int lr = l & 15, lc = l >> 4, lx = l & 7;

    int st = 0;
    for (int kt = 0; kt < KT; kt++) {
        CP_WAIT1();
        __syncthreads();
        if (kt + 2 < KT) {
            uint32_t base2 = sb + (uint32_t)((kt + 2) % 3) * STG1;
            load_tile<512, 128>(base2,          X,  m0, (kt + 2) * 64, HID);
            load_tile<512, 128>(base2 + 16384u, WG, n0, (kt + 2) * 64, HID);
            load_tile<512, 128>(base2 + 32768u, WU, n0, (kt + 2) * 64, HID);
        }
        CP_COMMIT();

        const uint32_t a_base = sb + (uint32_t)st * STG1            + (uint32_t)(wm + lr) * 128u;
        const uint32_t g_base = sb + (uint32_t)st * STG1 + 16384u   + (uint32_t)(wn + lr) * 128u;
        const uint32_t u_base = sb + (uint32_t)st * STG1 + 32768u   + (uint32_t)(wn + lr) * 128u;

        #pragma unroll
        for (int ks = 0; ks < 4; ks++) {
            const uint32_t ca = (uint32_t)(((ks * 2 + lc) ^ lx) << 4);
            uint32_t av[2][4], bg[2][4], bu[2][4];
            ldsm4(av[0], a_base + ca);
            ldsm4(av[1], a_base + 2048u + ca);
            ldsm4(bg[0], g_base + ca);
            ldsm4(bg[1], g_base + 2048u + ca);
            ldsm4(bu[0], u_base + ca);
            ldsm4(bu[1], u_base + 2048u + ca);
            #pragma unroll
            for (int mt = 0; mt < 2; mt++)
                #pragma unroll
                for (int nb = 0; nb < 2; nb++) {
                    mma16816(accg[mt][nb * 2 + 0], av[mt], bg[nb][0], bg[nb][2]);
                    mma16816(accg[mt][nb * 2 + 1], av[mt], bg[nb][1], bg[nb][3]);
                    mma16816(accu[mt][nb * 2 + 0], av[mt], bu[nb][0], bu[nb][2]);
                    mma16816(accu[mt][nb * 2 + 1], av[mt], bu[nb][1], bu[nb][3]);
                }
        }
        if (++st == 3) st = 0;
    }

    // SwiGLU epilogue -> fp16 h
    const int r0 = l >> 2, c0 = (l & 3) * 2;
    #pragma unroll
    for (int mt = 0; mt < 2; mt++) {
        int gm = m0 + wm + mt * 16 + r0;
        #pragma unroll
        for (int nf = 0; nf < 4; nf++) {
            int gn = n0 + wn + nf * 8 + c0;
            float sg0 = ag[gn], sg1 = ag[gn + 1];
            float su0 = au[gn], su1 = au[gn + 1];
            float* G = accg[mt][nf];
            float* U = accu[mt][nf];
            float g0 = G[0] * sg0, g1 = G[1] * sg1;
            float u0 = U[0] * su0, u1 = U[1] * su1;
            *reinterpret_cast<__half2*>(H + (size_t)gm * INTER + gn) =
                __floats2half2_rn(g0 * sigmoidf_fast(g0) * u0,
                                  g1 * sigmoidf_fast(g1) * u1);
            float g2 = G[2] * sg0, g3 = G[3] * sg1;
            float u2 = U[2] * su0, u3 = U[3] * su1;
            *reinterpret_cast<__half2*>(H + (size_t)(gm + 8) * INTER + gn) =
                __floats2half2_rn(g2 * sigmoidf_fast(g2) * u2,
                                  g3 * sigmoidf_fast(g3) * u3);
        }
    }
}

// ============================================================================
// GEMM2: out[m,n] = (sum_k h[m,k] * Wd[n,k]) * ad[n], fp32 out.
//   CTA tile 128x128, 512 threads / 16 warps (4m x 4n), warp tile 32x32,
//   3-stage pipeline, stage = 32 KB. Grid: x = n-tile (fast) so Wd (86 MB)
//   stays L2-resident; h (172 MB) streams from DRAM once.
// ============================================================================
#define STG2 32768u
#define SMEM2 (3 * 32768)

__global__ void __launch_bounds__(512, 1)
gemm2_kernel(const __half* __restrict__ A, const __half* __restrict__ B,
             const float* __restrict__ ad, float* __restrict__ out) {
    extern __shared__ char smem[];
    const uint32_t sb = smem_u32(smem);
    const int n0 = blockIdx.x * 128;      // n fast: weight-resident policy
    const int m0 = blockIdx.y * 128;
    const int l   = threadIdx.x & 31;
    const int wid = threadIdx.x >> 5;
    const int wm = (wid & 3) * 32;
    const int wn = (wid >> 2) * 32;
    const int KT = INTER >> 6;            // 172

    #pragma unroll
    for (int s = 0; s < 2; s++) {
        uint32_t base = sb + (uint32_t)s * STG2;
        load_tile<512, 128>(base,          A, m0, s * 64, INTER);
        load_tile<512, 128>(base + 16384u, B, n0, s * 64, INTER);
        CP_COMMIT();
    }

    float acc[2][4][4];
    #pragma unroll
    for (int i = 0; i < 2; i++)
        #pragma unroll
        for (int j = 0; j < 4; j++)
            #pragma unroll
            for (int q = 0; q < 4; q++) acc[i][j][q] = 0.f;

    const int lr = l & 15, lc = l >> 4, lx = l & 7;

    int st = 0;
    for (int kt = 0; kt < KT; kt++) {
        CP_WAIT1();
        __syncthreads();
        if (kt + 2 < KT) {
            uint32_t base2 = sb + (uint32_t)((kt + 2) % 3) * STG2;
            load_tile<512, 128>(base2,          A, m0, (kt + 2) * 64, INTER);
            load_tile<512, 128>(base2 + 16384u, B, n0, (kt + 2) * 64, INTER);
        }
        CP_COMMIT();

        const uint32_t a_base = sb + (uint32_t)st * STG2          + (uint32_t)(wm + lr) * 128u;
        const uint32_t b_base = sb + (uint32_t)st * STG2 + 16384u + (uint32_t)(wn + lr) * 128u;

        #pragma unroll
        for (int ks = 0; ks < 4; ks++) {
            const uint32_t ca = (uint32_t)(((ks * 2 + lc) ^ lx) << 4);
            uint32_t av[2][4], bv[2][4];
            ldsm4(av[0], a_base + ca);
            ldsm4(av[1], a_base + 2048u + ca);
            ldsm4(bv[0], b_base + ca);
            ldsm4(bv[1], b_base + 2048u + ca);
            #pragma unroll
            for (int mt = 0; mt < 2; mt++)
                #pragma unroll
                for (int nb = 0; nb < 2; nb++) {
                    mma16816(acc[mt][nb * 2 + 0], av[mt], bv[nb][0], bv[nb][2]);
                    mma16816(acc[mt][nb * 2 + 1], av[mt], bv[nb][1], bv[nb][3]);
                }
        }
        if (++st == 3) st = 0;
    }

    const int r0 = l >> 2, c0 = (l & 3) * 2;
    #pragma unroll
    for (int mt = 0; mt < 2; mt++) {
        int gm = m0 + wm + mt * 16 + r0;
        #pragma unroll
        for (int nf = 0; nf < 4; nf++) {
            int gn = n0 + wn + nf * 8 + c0;
            float s0 = ad[gn], s1 = ad[gn + 1];
            float* a4 = acc[mt][nf];
            *reinterpret_cast<float2*>(out + (size_t)gm * HID + gn) =
                make_float2(a4[0] * s0, a4[1] * s1);
            *reinterpret_cast<float2*>(out + (size_t)(gm + 8) * HID + gn) =
                make_float2(a4[2] * s0, a4[3] * s1);
        }
    }
}

// ============================================================================
// fp32 -> fp16 conversion (vectorized, grid-stride)
// ============================================================================
__global__ void cvt_f32_f16(const float* __restrict__ in, __half* __restrict__ out,
                            size_t n4) {
    size_t i = (size_t)blockIdx.x * blockDim.x + threadIdx.x;
    size_t stride = (size_t)gridDim.x * blockDim.x;
    for (; i < n4; i += stride) {
        float4 v = reinterpret_cast<const float4*>(in)[i];
        __half2 lo = __floats2half2_rn(v.x, v.y);
        __half2 hi = __floats2half2_rn(v.z, v.w);
        uint2 o;
        o.x = *reinterpret_cast<uint32_t*>(&lo);
        o.y = *reinterpret_cast<uint32_t*>(&hi);
        reinterpret_cast<uint2*>(out)[i] = o;
    }
}

// ============================================================================
// Host side
// ============================================================================
extern "C" void kernel_launch(void* const* d_in, const int* in_sizes, int n_in,
                              void* d_out, int out_size) {
    const float* x  = (const float*)d_in[0];
    const float* Wg = (const float*)d_in[1];
    const float* Wu = (const float*)d_in[2];
    const float* Wd = (const float*)d_in[3];
    const float* ag = (const float*)d_in[4];
    const float* au = (const float*)d_in[5];
    const float* ad = (const float*)d_in[6];
    float* out = (float*)d_out;

    void *px, *pwg, *pwu, *pwd, *ph;
    cudaGetSymbolAddress(&px,  g_x16);
    cudaGetSymbolAddress(&pwg, g_wg16);
    cudaGetSymbolAddress(&pwu, g_wu16);
    cudaGetSymbolAddress(&pwd, g_wd16);
    cudaGetSymbolAddress(&ph,  g_h16);

    cudaFuncSetAttribute(gemm1_fused,
                         cudaFuncAttributeMaxDynamicSharedMemorySize, SMEM1);
    cudaFuncSetAttribute(gemm2_kernel,
                         cudaFuncAttributeMaxDynamicSharedMemorySize, SMEM2);

    // fp32 -> fp16
    cvt_f32_f16<<<2048, 256>>>(x,  (__half*)px,  (size_t)MTOK  * HID   / 4);
    cvt_f32_f16<<<2048, 256>>>(Wg, (__half*)pwg, (size_t)INTER * HID   / 4);
    cvt_f32_f16<<<2048, 256>>>(Wu, (__half*)pwu, (size_t)INTER * HID   / 4);
    cvt_f32_f16<<<2048, 256>>>(Wd, (__half*)pwd, (size_t)HID   * INTER / 4);

    // Fused gate+up+SwiGLU -> h (fp16). m-tiles fast (x L2-resident).
    gemm1_fused<<<dim3(MTOK / 128, INTER / 128), 512, SMEM1>>>(
        (const __half*)px, (const __half*)pwg, (const __half*)pwu,
        ag, au, (__half*)ph);

    // out = (h @ Wd^T) * ad. n-tiles fast (Wd L2-resident).
    gemm2_kernel<<<dim3(HID / 128, MTOK / 128), 512, SMEM2>>>(
        (const __half*)ph, (const __half*)pwd, ad, out);
}

// round 7
// speedup vs baseline: 1.0708x; 1.0421x over previous
#include <cuda_runtime.h>
#include <cuda_fp16.h>
#include <cstdint>
#include <cstddef>

// ============================================================================
// out[8192,4096] = SwiGLU-MLP(x[8192,4096]) with ternary weights.
// mma.sync m16n8k16 fp16->fp32 (compute_100 PTX: no tcgen05 available).
//
// R4 (8w/CTA) and R6 (16w/CTA, fused) both measured ~352 TF/s -> mainloop is
// HMMA-pipe-saturated; the gap to ceiling is per-CTA serial overhead
// (prologue/syncthreads/epilogue) exposed at 1 CTA/SM. This round: 256-thread
// CTAs with tile 128Mx64N and __launch_bounds__(256,2) so TWO CTAs co-reside
// per SM and overlap each other's serial phases. Also merges the 4 cvt
// launches into 1 (graph = 3 launches -> ncu -s5 lands on a GEMM).
// ============================================================================
#define HID   4096
#define INTER 11008
#define MTOK  8192

// ============================================================================
// Device scratch (allocation rule: __device__ globals only)
// ============================================================================
__device__ __half g_x16 [(size_t)MTOK  * HID];     //  64 MB
__device__ __half g_wg16[(size_t)INTER * HID];     //  86 MB
__device__ __half g_wu16[(size_t)INTER * HID];     //  86 MB
__device__ __half g_wd16[(size_t)HID   * INTER];   //  86 MB
__device__ __half g_h16 [(size_t)MTOK  * INTER];   // 172 MB

// ============================================================================
// PTX helpers (sm_100-baseline: cp.async, ldmatrix, mma.sync)
// ============================================================================
__device__ __forceinline__ uint32_t smem_u32(const void* p) {
    uint32_t a;
    asm("{ .reg .u64 t; cvta.to.shared.u64 t, %1; cvt.u32.u64 %0, t; }"
        : "=r"(a) : "l"(p));
    return a;
}

__device__ __forceinline__ void cp_async16(uint32_t s, const void* g) {
    asm volatile("cp.async.cg.shared.global [%0], [%1], 16;" :: "r"(s), "l"(g));
}
#define CP_COMMIT() asm volatile("cp.async.commit_group;" ::: "memory")
#define CP_WAIT1()  asm volatile("cp.async.wait_group 1;"  ::: "memory")

__device__ __forceinline__ void ldsm4(uint32_t* r, uint32_t addr) {
    asm volatile("ldmatrix.sync.aligned.m8n8.x4.shared.b16 {%0,%1,%2,%3}, [%4];"
        : "=r"(r[0]), "=r"(r[1]), "=r"(r[2]), "=r"(r[3]) : "r"(addr));
}

__device__ __forceinline__ void mma16816(float* c, const uint32_t* a,
                                         uint32_t b0, uint32_t b1) {
    asm volatile(
        "mma.sync.aligned.m16n8k16.row.col.f32.f16.f16.f32 "
        "{%0,%1,%2,%3}, {%4,%5,%6,%7}, {%8,%9}, {%0,%1,%2,%3};"
        : "+f"(c[0]), "+f"(c[1]), "+f"(c[2]), "+f"(c[3])
        : "r"(a[0]), "r"(a[1]), "r"(a[2]), "r"(a[3]), "r"(b0), "r"(b1));
}

// ============================================================================
// Tile loader: R rows x 64 halves (128 B) per row, XOR-swizzled smem layout.
// smem_off = row*128 + ((chunk ^ (row&7)) << 4). Conflict-free for both the
// cp.async stores and ldmatrix reads. Verified correct in R4/R6.
// ============================================================================
template<int THREADS, int R>
__device__ __forceinline__ void load_tile(uint32_t sbase, const __half* g,
                                          int row0, int k0, int ldk) {
    int t = threadIdx.x;
    #pragma unroll
    for (int i = 0; i < R * 8 / THREADS; i++) {
        int ch = t + i * THREADS;
        int r = ch >> 3, c = ch & 7;
        cp_async16(sbase + r * 128 + (uint32_t)((c ^ (r & 7)) << 4),
                   g + (size_t)(row0 + r) * ldk + k0 + c * 8);
    }
}

__device__ __forceinline__ float sigmoidf_fast(float v) {
    return 1.0f / (1.0f + __expf(-v));
}

// ============================================================================
// Fused gate+up GEMM + SwiGLU.  CTA tile 128(M) x 64(N), BOTH matrices.
// 256 threads = 8 warps (4m x 2n), warp tile 32x32 per matrix (64 acc regs).
// 3-stage cp.async pipeline, stage = 32 KB (A 16K + Wg 8K + Wu 8K) = 96 KB
// total -> 2 CTAs/SM. Epilogue: h = silu(g*ag)*(u*au) -> fp16.
// Grid: x = m-tile (fast) so x (64 MB fp16) stays L2-resident.
// ============================================================================
#define STG1 32768u
#define SMEM1 (3 * 32768)

__global__ void __launch_bounds__(256, 2)
gemm1_fused(const __half* __restrict__ X, const __half* __restrict__ WG,
            const __half* __restrict__ WU, const float* __restrict__ ag,
            const float* __restrict__ au, __half* __restrict__ H) {
    extern __shared__ char smem[];
    const uint32_t sb = smem_u32(smem);
    const int m0 = blockIdx.x * 128;
    const int n0 = blockIdx.y * 64;
    const int l   = threadIdx.x & 31;
    const int wid = threadIdx.x >> 5;
    const int wm = (wid & 3) * 32;
    const int wn = (wid >> 2) * 32;
    const int KT = HID >> 6;

    // prologue: stages 0, 1
    #pragma unroll
    for (int s = 0; s < 2; s++) {
        uint32_t base = sb + (uint32_t)s * STG1;
        load_tile<256, 128>(base,           X,  m0, s * 64, HID);
        load_tile<256, 64> (base + 16384u,  WG, n0, s * 64, HID);
        load_tile<256, 64> (base + 24576u,  WU, n0, s * 64, HID);
        CP_COMMIT();
    }

    float accg[2][4][4], accu[2][4][4];
    #pragma unroll
    for (int i = 0; i < 2; i++)
        #pragma unroll
        for (int j = 0; j < 4; j++)
            #pragma unroll
            for (int q = 0; q < 4; q++) { accg[i][j][q] = 0.f; accu[i][j][q] = 0.f; }

    const int lr = l & 15, lc = l >> 4, lx = l & 7;

    int st = 0;
    for (int kt = 0; kt < KT; kt++) {
        CP_WAIT1();
        __syncthreads();
        if (kt + 2 < KT) {
            uint32_t base2 = sb + (uint32_t)((kt + 2) % 3) * STG1;
            load_tile<256, 128>(base2,          X,  m0, (kt + 2) * 64, HID);
            load_tile<256, 64> (base2 + 16384u, WG, n0, (kt + 2) * 64, HID);
            load_tile<256, 64> (base2 + 24576u, WU, n0, (kt + 2) * 64, HID);
        }
        CP_COMMIT();

        const uint32_t a_base = sb + (uint32_t)st * STG1           + (uint32_t)(wm + lr) * 128u;
        const uint32_t g_base = sb + (uint32_t)st * STG1 + 16384u  + (uint32_t)(wn + lr) * 128u;
        const uint32_t u_base = sb + (uint32_t)st * STG1 + 24576u  + (uint32_t)(wn + lr) * 128u;

        #pragma unroll
        for (int ks = 0; ks < 4; ks++) {
            const uint32_t ca = (uint32_t)(((ks * 2 + lc) ^ lx) << 4);
            uint32_t av[2][4], bg[2][4], bu[2][4];
            ldsm4(av[0], a_base + ca);
            ldsm4(av[1], a_base + 2048u + ca);
            ldsm4(bg[0], g_base + ca);
            ldsm4(bg[1], g_base + 2048u + ca);
            ldsm4(bu[0], u_base + ca);
            ldsm4(bu[1], u_base + 2048u + ca);
            #pragma unroll
            for (int mt = 0; mt < 2; mt++)
                #pragma unroll
                for (int nb = 0; nb < 2; nb++) {
                    mma16816(accg[mt][nb * 2 + 0], av[mt], bg[nb][0], bg[nb][2]);
                    mma16816(accg[mt][nb * 2 + 1], av[mt], bg[nb][1], bg[nb][3]);
                    mma16816(accu[mt][nb * 2 + 0], av[mt], bu[nb][0], bu[nb][2]);
                    mma16816(accu[mt][nb * 2 + 1], av[mt], bu[nb][1], bu[nb][3]);
                }
        }
        if (++st == 3) st = 0;
    }

    // SwiGLU epilogue -> fp16 h
    const int r0 = l >> 2, c0 = (l & 3) * 2;
    #pragma unroll
    for (int mt = 0; mt < 2; mt++) {
        int gm = m0 + wm + mt * 16 + r0;
        #pragma unroll
        for (int nf = 0; nf < 4; nf++) {
            int gn = n0 + wn + nf * 8 + c0;
            float sg0 = ag[gn], sg1 = ag[gn + 1];
            float su0 = au[gn], su1 = au[gn + 1];
            float* G = accg[mt][nf];
            float* U = accu[mt][nf];
            float g0 = G[0] * sg0, g1 = G[1] * sg1;
            float u0 = U[0] * su0, u1 = U[1] * su1;
            *reinterpret_cast<__half2*>(H + (size_t)gm * INTER + gn) =
                __floats2half2_rn(g0 * sigmoidf_fast(g0) * u0,
                                  g1 * sigmoidf_fast(g1) * u1);
            float g2 = G[2] * sg0, g3 = G[3] * sg1;
            float u2 = U[2] * su0, u3 = U[3] * su1;
            *reinterpret_cast<__half2*>(H + (size_t)(gm + 8) * INTER + gn) =
                __floats2half2_rn(g2 * sigmoidf_fast(g2) * u2,
                                  g3 * sigmoidf_fast(g3) * u3);
        }
    }
}

// ============================================================================
// GEMM2: out[m,n] = (sum_k h[m,k] * Wd[n,k]) * ad[n], fp32 out.
// CTA tile 128x64, 256 threads / 8 warps (4m x 2n), warp tile 32x32, 3-stage
// pipeline, stage = 24 KB -> 72 KB total -> 2 CTAs/SM.
// Grid: x = n-tile (fast) so Wd (86 MB) stays L2-resident; h streams once.
// ============================================================================
#define STG2 24576u
#define SMEM2 (3 * 24576)

__global__ void __launch_bounds__(256, 2)
gemm2_kernel(const __half* __restrict__ A, const __half* __restrict__ B,
             const float* __restrict__ ad, float* __restrict__ out) {
    extern __shared__ char smem[];
    const uint32_t sb = smem_u32(smem);
    const int n0 = blockIdx.x * 64;       // n fast: weight-resident policy
    const int m0 = blockIdx.y * 128;
    const int l   = threadIdx.x & 31;
    const int wid = threadIdx.x >> 5;
    const int wm = (wid & 3) * 32;
    const int wn = (wid >> 2) * 32;
    const int KT = INTER >> 6;            // 172

    #pragma unroll
    for (int s = 0; s < 2; s++) {
        uint32_t base = sb + (uint32_t)s * STG2;
        load_tile<256, 128>(base,          A, m0, s * 64, INTER);
        load_tile<256, 64> (base + 16384u, B, n0, s * 64, INTER);
        CP_COMMIT();
    }

    float acc[2][4][4];
    #pragma unroll
    for (int i = 0; i < 2; i++)
        #pragma unroll
        for (int j = 0; j < 4; j++)
            #pragma unroll
            for (int q = 0; q < 4; q++) acc[i][j][q] = 0.f;

    const int lr = l & 15, lc = l >> 4, lx = l & 7;

    int st = 0;
    for (int kt = 0; kt < KT; kt++) {
        CP_WAIT1();
        __syncthreads();
        if (kt + 2 < KT) {
            uint32_t base2 = sb + (uint32_t)((kt + 2) % 3) * STG2;
            load_tile<256, 128>(base2,          A, m0, (kt + 2) * 64, INTER);
            load_tile<256, 64> (base2 + 16384u, B, n0, (kt + 2) * 64, INTER);
        }
        CP_COMMIT();

        const uint32_t a_base = sb + (uint32_t)st * STG2          + (uint32_t)(wm + lr) * 128u;
        const uint32_t b_base = sb + (uint32_t)st * STG2 + 16384u + (uint32_t)(wn + lr) * 128u;

        #pragma unroll
        for (int ks = 0; ks < 4; ks++) {
            const uint32_t ca = (uint32_t)(((ks * 2 + lc) ^ lx) << 4);
            uint32_t av[2][4], bv[2][4];
            ldsm4(av[0], a_base + ca);
            ldsm4(av[1], a_base + 2048u + ca);
            ldsm4(bv[0], b_base + ca);
            ldsm4(bv[1], b_base + 2048u + ca);
            #pragma unroll
            for (int mt = 0; mt < 2; mt++)
                #pragma unroll
                for (int nb = 0; nb < 2; nb++) {
                    mma16816(acc[mt][nb * 2 + 0], av[mt], bv[nb][0], bv[nb][2]);
                    mma16816(acc[mt][nb * 2 + 1], av[mt], bv[nb][1], bv[nb][3]);
                }
        }
        if (++st == 3) st = 0;
    }

    const int r0 = l >> 2, c0 = (l & 3) * 2;
    #pragma unroll
    for (int mt = 0; mt < 2; mt++) {
        int gm = m0 + wm + mt * 16 + r0;
        #pragma unroll
        for (int nf = 0; nf < 4; nf++) {
            int gn = n0 + wn + nf * 8 + c0;
            float s0 = ad[gn], s1 = ad[gn + 1];
            float* a4 = acc[mt][nf];
            *reinterpret_cast<float2*>(out + (size_t)gm * HID + gn) =
                make_float2(a4[0] * s0, a4[1] * s1);
            *reinterpret_cast<float2*>(out + (size_t)(gm + 8) * HID + gn) =
                make_float2(a4[2] * s0, a4[3] * s1);
        }
    }
}

// ============================================================================
// Merged fp32 -> fp16 conversion: all four tensors in one launch.
// (Also collapses the graph to 3 launches so ncu -s5 captures a GEMM.)
// ============================================================================
__global__ void cvt_all(const float* __restrict__ i0, __half* __restrict__ o0, size_t n0,
                        const float* __restrict__ i1, __half* __restrict__ o1, size_t n1,
                        const float* __restrict__ i2, __half* __restrict__ o2, size_t n2,
                        const float* __restrict__ i3, __half* __restrict__ o3, size_t n3) {
    const size_t stride = (size_t)gridDim.x * blockDim.x;
    const size_t t0 = (size_t)blockIdx.x * blockDim.x + threadIdx.x;
    const float*  in[4]  = {i0, i1, i2, i3};
    __half*       outp[4] = {o0, o1, o2, o3};
    const size_t  n[4]   = {n0, n1, n2, n3};
    #pragma unroll
    for (int s = 0; s < 4; s++) {
        const float* src = in[s];
        __half* dst = outp[s];
        for (size_t i = t0; i < n[s]; i += stride) {
            float4 v = reinterpret_cast<const float4*>(src)[i];
            __half2 lo = __floats2half2_rn(v.x, v.y);
            __half2 hi = __floats2half2_rn(v.z, v.w);
            uint2 o;
            o.x = *reinterpret_cast<uint32_t*>(&lo);
            o.y = *reinterpret_cast<uint32_t*>(&hi);
            reinterpret_cast<uint2*>(dst)[i] = o;
        }
    }
}

// ============================================================================
// Host side
// ============================================================================
extern "C" void kernel_launch(void* const* d_in, const int* in_sizes, int n_in,
                              void* d_out, int out_size) {
    const float* x  = (const float*)d_in[0];
    const float* Wg = (const float*)d_in[1];
    const float* Wu = (const float*)d_in[2];
    const float* Wd = (const float*)d_in[3];
    const float* ag = (const float*)d_in[4];
    const float* au = (const float*)d_in[5];
    const float* ad = (const float*)d_in[6];
    float* out = (float*)d_out;

    void *px, *pwg, *pwu, *pwd, *ph;
    cudaGetSymbolAddress(&px,  g_x16);
    cudaGetSymbolAddress(&pwg, g_wg16);
    cudaGetSymbolAddress(&pwu, g_wu16);
    cudaGetSymbolAddress(&pwd, g_wd16);
    cudaGetSymbolAddress(&ph,  g_h16);

    cudaFuncSetAttribute(gemm1_fused,
                         cudaFuncAttributeMaxDynamicSharedMemorySize, SMEM1);
    cudaFuncSetAttribute(gemm2_kernel,
                         cudaFuncAttributeMaxDynamicSharedMemorySize, SMEM2);

    // All fp32 -> fp16 conversions in one launch
    cvt_all<<<2048, 256>>>(
        x,  (__half*)px,  (size_t)MTOK  * HID   / 4,
        Wg, (__half*)pwg, (size_t)INTER * HID   / 4,
        Wu, (__half*)pwu, (size_t)INTER * HID   / 4,
        Wd, (__half*)pwd, (size_t)HID   * INTER / 4);

    // Fused gate+up+SwiGLU -> h (fp16). m-tiles fast (x L2-resident).
    gemm1_fused<<<dim3(MTOK / 128, INTER / 64), 256, SMEM1>>>(
        (const __half*)px, (const __half*)pwg, (const __half*)pwu,
        ag, au, (__half*)ph);

    // out = (h @ Wd^T) * ad. n-tiles fast (Wd L2-resident).
    gemm2_kernel<<<dim3(HID / 64, MTOK / 128), 256, SMEM2>>>(
        (const __half*)ph, (const __half*)pwd, ad, out);
}

// round 8
// speedup vs baseline: 1.1163x; 1.0425x over previous
#include <cuda_runtime.h>
#include <cuda_fp16.h>
#include <cstdint>
#include <cstddef>

// ============================================================================
// out[8192,4096] = SwiGLU-MLP(x[8192,4096]) with ternary weights.
// mma.sync m16n8k16 fp16->fp32 (compute_100 PTX: no tcgen05 available).
//
// History: R4 6640us (8w/CTA, split gate/up). R6 6461us (fused, 16w/CTA).
// R7 6200us (256thr CTAs, 2 CTAs/SM, merged cvt) -> GEMM ~365 TF/s.
// This round: GEMM2 retiled to CTA 128x128 / warp 32x64 (same 256 threads,
// still 2 CTAs/SM at 96KB smem) -> 16 mma per 6 ldsm4 (was 8 per 4), half
// the sync/prologue events per output, half the L2 h-traffic. GEMM1 kept
// (register budget of dual accumulators blocks a wider warp tile there).
// ============================================================================
#define HID   4096
#define INTER 11008
#define MTOK  8192

// ============================================================================
// Device scratch (allocation rule: __device__ globals only)
// ============================================================================
__device__ __half g_x16 [(size_t)MTOK  * HID];     //  64 MB
__device__ __half g_wg16[(size_t)INTER * HID];     //  86 MB
__device__ __half g_wu16[(size_t)INTER * HID];     //  86 MB
__device__ __half g_wd16[(size_t)HID   * INTER];   //  86 MB
__device__ __half g_h16 [(size_t)MTOK  * INTER];   // 172 MB

// ============================================================================
// PTX helpers (sm_100-baseline: cp.async, ldmatrix, mma.sync)
// ============================================================================
__device__ __forceinline__ uint32_t smem_u32(const void* p) {
    uint32_t a;
    asm("{ .reg .u64 t; cvta.to.shared.u64 t, %1; cvt.u32.u64 %0, t; }"
        : "=r"(a) : "l"(p));
    return a;
}

__device__ __forceinline__ void cp_async16(uint32_t s, const void* g) {
    asm volatile("cp.async.cg.shared.global [%0], [%1], 16;" :: "r"(s), "l"(g));
}
#define CP_COMMIT() asm volatile("cp.async.commit_group;" ::: "memory")
#define CP_WAIT1()  asm volatile("cp.async.wait_group 1;"  ::: "memory")

__device__ __forceinline__ void ldsm4(uint32_t* r, uint32_t addr) {
    asm volatile("ldmatrix.sync.aligned.m8n8.x4.shared.b16 {%0,%1,%2,%3}, [%4];"
        : "=r"(r[0]), "=r"(r[1]), "=r"(r[2]), "=r"(r[3]) : "r"(addr));
}

__device__ __forceinline__ void mma16816(float* c, const uint32_t* a,
                                         uint32_t b0, uint32_t b1) {
    asm volatile(
        "mma.sync.aligned.m16n8k16.row.col.f32.f16.f16.f32 "
        "{%0,%1,%2,%3}, {%4,%5,%6,%7}, {%8,%9}, {%0,%1,%2,%3};"
        : "+f"(c[0]), "+f"(c[1]), "+f"(c[2]), "+f"(c[3])
        : "r"(a[0]), "r"(a[1]), "r"(a[2]), "r"(a[3]), "r"(b0), "r"(b1));
}

// ============================================================================
// Tile loader: R rows x 64 halves (128 B) per row, XOR-swizzled smem layout.
// smem_off = row*128 + ((chunk ^ (row&7)) << 4). Conflict-free for both the
// cp.async stores and ldmatrix reads. Verified correct in R4/R6/R7.
// ============================================================================
template<int THREADS, int R>
__device__ __forceinline__ void load_tile(uint32_t sbase, const __half* g,
                                          int row0, int k0, int ldk) {
    int t = threadIdx.x;
    #pragma unroll
    for (int i = 0; i < R * 8 / THREADS; i++) {
        int ch = t + i * THREADS;
        int r = ch >> 3, c = ch & 7;
        cp_async16(sbase + r * 128 + (uint32_t)((c ^ (r & 7)) << 4),
                   g + (size_t)(row0 + r) * ldk + k0 + c * 8);
    }
}

__device__ __forceinline__ float sigmoidf_fast(float v) {
    return 1.0f / (1.0f + __expf(-v));
}

// ============================================================================
// Fused gate+up GEMM + SwiGLU.  CTA tile 128(M) x 64(N), BOTH matrices.
// 256 threads = 8 warps (4m x 2n), warp tile 32x32 per matrix (64 acc regs).
// 3-stage cp.async pipeline, stage = 32 KB -> 96 KB total -> 2 CTAs/SM.
// Grid: x = m-tile (fast) so x (64 MB fp16) stays L2-resident.  (Unchanged
// from R7 — measured passing at rel_err 3.63e-4.)
// ============================================================================
#define STG1 32768u
#define SMEM1 (3 * 32768)

__global__ void __launch_bounds__(256, 2)
gemm1_fused(const __half* __restrict__ X, const __half* __restrict__ WG,
            const __half* __restrict__ WU, const float* __restrict__ ag,
            const float* __restrict__ au, __half* __restrict__ H) {
    extern __shared__ char smem[];
    const uint32_t sb = smem_u32(smem);
    const int m0 = blockIdx.x * 128;
    const int n0 = blockIdx.y * 64;
    const int l   = threadIdx.x & 31;
    const int wid = threadIdx.x >> 5;
    const int wm = (wid & 3) * 32;
    const int wn = (wid >> 2) * 32;
    const int KT = HID >> 6;

    #pragma unroll
    for (int s = 0; s < 2; s++) {
        uint32_t base = sb + (uint32_t)s * STG1;
        load_tile<256, 128>(base,           X,  m0, s * 64, HID);
        load_tile<256, 64> (base + 16384u,  WG, n0, s * 64, HID);
        load_tile<256, 64> (base + 24576u,  WU, n0, s * 64, HID);
        CP_COMMIT();
    }

    float accg[2][4][4], accu[2][4][4];
    #pragma unroll
    for (int i = 0; i < 2; i++)
        #pragma unroll
        for (int j = 0; j < 4; j++)
            #pragma unroll
            for (int q = 0; q < 4; q++) { accg[i][j][q] = 0.f; accu[i][j][q] = 0.f; }

    const int lr = l & 15, lc = l >> 4, lx = l & 7;

    int st = 0;
    for (int kt = 0; kt < KT; kt++) {
        CP_WAIT1();
        __syncthreads();
        if (kt + 2 < KT) {
            uint32_t base2 = sb + (uint32_t)((kt + 2) % 3) * STG1;
            load_tile<256, 128>(base2,          X,  m0, (kt + 2) * 64, HID);
            load_tile<256, 64> (base2 + 16384u, WG, n0, (kt + 2) * 64, HID);
            load_tile<256, 64> (base2 + 24576u, WU, n0, (kt + 2) * 64, HID);
        }
        CP_COMMIT();

        const uint32_t a_base = sb + (uint32_t)st * STG1           + (uint32_t)(wm + lr) * 128u;
        const uint32_t g_base = sb + (uint32_t)st * STG1 + 16384u  + (uint32_t)(wn + lr) * 128u;
        const uint32_t u_base = sb + (uint32_t)st * STG1 + 24576u  + (uint32_t)(wn + lr) * 128u;

        #pragma unroll
        for (int ks = 0; ks < 4; ks++) {
            const uint32_t ca = (uint32_t)(((ks * 2 + lc) ^ lx) << 4);
            uint32_t av[2][4], bg[2][4], bu[2][4];
            ldsm4(av[0], a_base + ca);
            ldsm4(av[1], a_base + 2048u + ca);
            ldsm4(bg[0], g_base + ca);
            ldsm4(bg[1], g_base + 2048u + ca);
            ldsm4(bu[0], u_base + ca);
            ldsm4(bu[1], u_base + 2048u + ca);
            #pragma unroll
            for (int mt = 0; mt < 2; mt++)
                #pragma unroll
                for (int nb = 0; nb < 2; nb++) {
                    mma16816(accg[mt][nb * 2 + 0], av[mt], bg[nb][0], bg[nb][2]);
                    mma16816(accg[mt][nb * 2 + 1], av[mt], bg[nb][1], bg[nb][3]);
                    mma16816(accu[mt][nb * 2 + 0], av[mt], bu[nb][0], bu[nb][2]);
                    mma16816(accu[mt][nb * 2 + 1], av[mt], bu[nb][1], bu[nb][3]);
                }
        }
        if (++st == 3) st = 0;
    }

    // SwiGLU epilogue -> fp16 h
    const int r0 = l >> 2, c0 = (l & 3) * 2;
    #pragma unroll
    for (int mt = 0; mt < 2; mt++) {
        int gm = m0 + wm + mt * 16 + r0;
        #pragma unroll
        for (int nf = 0; nf < 4; nf++) {
            int gn = n0 + wn + nf * 8 + c0;
            float sg0 = ag[gn], sg1 = ag[gn + 1];
            float su0 = au[gn], su1 = au[gn + 1];
            float* G = accg[mt][nf];
            float* U = accu[mt][nf];
            float g0 = G[0] * sg0, g1 = G[1] * sg1;
            float u0 = U[0] * su0, u1 = U[1] * su1;
            *reinterpret_cast<__half2*>(H + (size_t)gm * INTER + gn) =
                __floats2half2_rn(g0 * sigmoidf_fast(g0) * u0,
                                  g1 * sigmoidf_fast(g1) * u1);
            float g2 = G[2] * sg0, g3 = G[3] * sg1;
            float u2 = U[2] * su0, u3 = U[3] * su1;
            *reinterpret_cast<__half2*>(H + (size_t)(gm + 8) * INTER + gn) =
                __floats2half2_rn(g2 * sigmoidf_fast(g2) * u2,
                                  g3 * sigmoidf_fast(g3) * u3);
        }
    }
}

// ============================================================================
// GEMM2: out[m,n] = (sum_k h[m,k] * Wd[n,k]) * ad[n], fp32 out.
// RETILED: CTA 128x128, 256 threads / 8 warps (4m x 2n), warp tile 32x64.
// Per k16-step: 16 mma / 6 ldsm4 (was 8/4). Stage = 32 KB (A 16K + B 16K),
// 3 stages = 96 KB -> still 2 CTAs/SM. Regs ~110/thread (64 acc + 24 frag).
// Grid: x = n-tile (fast) so Wd (86 MB) stays L2-resident; h streams once.
// ============================================================================
#define STG2 32768u
#define SMEM2 (3 * 32768)

__global__ void __launch_bounds__(256, 2)
gemm2_kernel(const __half* __restrict__ A, const __half* __restrict__ B,
             const float* __restrict__ ad, float* __restrict__ out) {
    extern __shared__ char smem[];
    const uint32_t sb = smem_u32(smem);
    const int n0 = blockIdx.x * 128;      // n fast: weight-resident policy
    const int m0 = blockIdx.y * 128;
    const int l   = threadIdx.x & 31;
    const int wid = threadIdx.x >> 5;
    const int wm = (wid & 3) * 32;        // 4 m-positions
    const int wn = (wid >> 2) * 64;       // 2 n-positions, 64 wide each
    const int KT = INTER >> 6;            // 172

    #pragma unroll
    for (int s = 0; s < 2; s++) {
        uint32_t base = sb + (uint32_t)s * STG2;
        load_tile<256, 128>(base,          A, m0, s * 64, INTER);
        load_tile<256, 128>(base + 16384u, B, n0, s * 64, INTER);
        CP_COMMIT();
    }

    float acc[2][8][4];
    #pragma unroll
    for (int i = 0; i < 2; i++)
        #pragma unroll
        for (int j = 0; j < 8; j++)
            #pragma unroll
            for (int q = 0; q < 4; q++) acc[i][j][q] = 0.f;

    const int lr = l & 15, lc = l >> 4, lx = l & 7;

    int st = 0;
    for (int kt = 0; kt < KT; kt++) {
        CP_WAIT1();
        __syncthreads();
        if (kt + 2 < KT) {
            uint32_t base2 = sb + (uint32_t)((kt + 2) % 3) * STG2;
            load_tile<256, 128>(base2,          A, m0, (kt + 2) * 64, INTER);
            load_tile<256, 128>(base2 + 16384u, B, n0, (kt + 2) * 64, INTER);
        }
        CP_COMMIT();

        const uint32_t a_base = sb + (uint32_t)st * STG2          + (uint32_t)(wm + lr) * 128u;
        const uint32_t b_base = sb + (uint32_t)st * STG2 + 16384u + (uint32_t)(wn + lr) * 128u;

        #pragma unroll
        for (int ks = 0; ks < 4; ks++) {
            const uint32_t ca = (uint32_t)(((ks * 2 + lc) ^ lx) << 4);
            uint32_t av[2][4], bv[4][4];
            ldsm4(av[0], a_base + ca);
            ldsm4(av[1], a_base + 2048u + ca);
            #pragma unroll
            for (int nb = 0; nb < 4; nb++)
                ldsm4(bv[nb], b_base + (uint32_t)nb * 2048u + ca);
            #pragma unroll
            for (int mt = 0; mt < 2; mt++)
                #pragma unroll
                for (int nb = 0; nb < 4; nb++) {
                    mma16816(acc[mt][nb * 2 + 0], av[mt], bv[nb][0], bv[nb][2]);
                    mma16816(acc[mt][nb * 2 + 1], av[mt], bv[nb][1], bv[nb][3]);
                }
        }
        if (++st == 3) st = 0;
    }

    const int r0 = l >> 2, c0 = (l & 3) * 2;
    #pragma unroll
    for (int mt = 0; mt < 2; mt++) {
        int gm = m0 + wm + mt * 16 + r0;
        #pragma unroll
        for (int nf = 0; nf < 8; nf++) {
            int gn = n0 + wn + nf * 8 + c0;
            float s0 = ad[gn], s1 = ad[gn + 1];
            float* a4 = acc[mt][nf];
            *reinterpret_cast<float2*>(out + (size_t)gm * HID + gn) =
                make_float2(a4[0] * s0, a4[1] * s1);
            *reinterpret_cast<float2*>(out + (size_t)(gm + 8) * HID + gn) =
                make_float2(a4[2] * s0, a4[3] * s1);
        }
    }
}

// ============================================================================
// Merged fp32 -> fp16 conversion: all four tensors in one launch.
// ============================================================================
__global__ void cvt_all(const float* __restrict__ i0, __half* __restrict__ o0, size_t n0,
                        const float* __restrict__ i1, __half* __restrict__ o1, size_t n1,
                        const float* __restrict__ i2, __half* __restrict__ o2, size_t n2,
                        const float* __restrict__ i3, __half* __restrict__ o3, size_t n3) {
    const size_t stride = (size_t)gridDim.x * blockDim.x;
    const size_t t0 = (size_t)blockIdx.x * blockDim.x + threadIdx.x;
    const float*  in[4]   = {i0, i1, i2, i3};
    __half*       outp[4] = {o0, o1, o2, o3};
    const size_t  n[4]    = {n0, n1, n2, n3};
    #pragma unroll
    for (int s = 0; s < 4; s++) {
        const float* src = in[s];
        __half* dst = outp[s];
        for (size_t i = t0; i < n[s]; i += stride) {
            float4 v = reinterpret_cast<const float4*>(src)[i];
            __half2 lo = __floats2half2_rn(v.x, v.y);
            __half2 hi = __floats2half2_rn(v.z, v.w);
            uint2 o;
            o.x = *reinterpret_cast<uint32_t*>(&lo);
            o.y = *reinterpret_cast<uint32_t*>(&hi);
            reinterpret_cast<uint2*>(dst)[i] = o;
        }
    }
}

// ============================================================================
// Host side
// ============================================================================
extern "C" void kernel_launch(void* const* d_in, const int* in_sizes, int n_in,
                              void* d_out, int out_size) {
    const float* x  = (const float*)d_in[0];
    const float* Wg = (const float*)d_in[1];
    const float* Wu = (const float*)d_in[2];
    const float* Wd = (const float*)d_in[3];
    const float* ag = (const float*)d_in[4];
    const float* au = (const float*)d_in[5];
    const float* ad = (const float*)d_in[6];
    float* out = (float*)d_out;

    void *px, *pwg, *pwu, *pwd, *ph;
    cudaGetSymbolAddress(&px,  g_x16);
    cudaGetSymbolAddress(&pwg, g_wg16);
    cudaGetSymbolAddress(&pwu, g_wu16);
    cudaGetSymbolAddress(&pwd, g_wd16);
    cudaGetSymbolAddress(&ph,  g_h16);

    cudaFuncSetAttribute(gemm1_fused,
                         cudaFuncAttributeMaxDynamicSharedMemorySize, SMEM1);
    cudaFuncSetAttribute(gemm2_kernel,
                         cudaFuncAttributeMaxDynamicSharedMemorySize, SMEM2);

    // All fp32 -> fp16 conversions in one launch
    cvt_all<<<3072, 256>>>(
        x,  (__half*)px,  (size_t)MTOK  * HID   / 4,
        Wg, (__half*)pwg, (size_t)INTER * HID   / 4,
        Wu, (__half*)pwu, (size_t)INTER * HID   / 4,
        Wd, (__half*)pwd, (size_t)HID   * INTER / 4);

    // Fused gate+up+SwiGLU -> h (fp16). m-tiles fast (x L2-resident).
    gemm1_fused<<<dim3(MTOK / 128, INTER / 64), 256, SMEM1>>>(
        (const __half*)px, (const __half*)pwg, (const __half*)pwu,
        ag, au, (__half*)ph);

    // out = (h @ Wd^T) * ad. n-tiles fast (Wd L2-resident).
    gemm2_kernel<<<dim3(HID / 128, MTOK / 128), 256, SMEM2>>>(
        (const __half*)ph, (const __half*)pwd, ad, out);
}